// round 10
// baseline (speedup 1.0000x reference)
#include <cuda_runtime.h>
#include <cuda_bf16.h>
#include <cstdint>

// Weighted AUC, single fused kernel. Loads via cp.async.cg (LDGSTS) into a
// per-thread-private 3-stage smem pipeline: unbounded async depth keeps DRAM
// saturated independent of register scoreboard / occupancy. Labels are 0/1:
// one smem ATOMS per element into [tp NB | fp NB], bin+half folded into
// 2 FMA + F2I. area = sum_b fp[b]*(TP_above(b)+0.5*tp[b]);
// auc = area/(TP_tot*FP_tot). Last block per task finalizes and re-zeros
// global state so every graph replay is identical.

#define T_TASKS 16
#define NB 4096
#define NPT 2097152
#define N4 (NPT / 4)           // 524288 float4 per task
#define CHUNKS 37              // 592 blocks = 2 exact waves at 2 blocks/SM
#define PER_CHUNK 14171        // ceil(N4/37)
#define THREADS 512
#define BINS_PT (NB / THREADS)
#define STAGES 3

#define SMEM_BYTES (2 * NB * 4 + STAGES * 3 * THREADS * 16)   // 32KB + 72KB

__device__ float        g_hist[T_TASKS * 2 * NB];   // zero-init at load
__device__ unsigned int g_count[T_TASKS];           // zero-init at load

__device__ __forceinline__ void cp16(void* smem_dst, const void* gsrc) {
    unsigned a = (unsigned)__cvta_generic_to_shared(smem_dst);
    asm volatile("cp.async.cg.shared.global [%0], [%1], 16;\n" :: "r"(a), "l"(gsrc));
}
#define CP_COMMIT() asm volatile("cp.async.commit_group;\n" ::: "memory")
#define CP_WAIT2()  asm volatile("cp.async.wait_group 2;\n" ::: "memory")
#define CP_WAIT0()  asm volatile("cp.async.wait_group 0;\n" ::: "memory")

__global__ void __launch_bounds__(THREADS, 2) auc_kernel(
    const float4* __restrict__ pp, const float4* __restrict__ ll,
    const float4* __restrict__ ww, float* __restrict__ out)
{
    extern __shared__ __align__(16) float sh[];          // [2*NB] hist
    float4* stage = (float4*)(sh + 2 * NB);              // [STAGES][3][THREADS]

    const int task = blockIdx.y;
    const int t    = threadIdx.x;

    for (int i = t; i < 2 * NB; i += THREADS) sh[i] = 0.0f;
    __syncthreads();

    // ---- histogram phase: per-thread 3-deep cp.async pipeline ----
    {
        const int start = blockIdx.x * PER_CHUNK;
        const int end   = (start + PER_CHUNK < N4) ? start + PER_CHUNK : N4;
        const int base  = task * N4 + start;
        const int cnt   = end - start;
        const int KTOT  = (cnt + THREADS - 1) / THREADS;

        float4* st = stage + t;                          // this thread's lane
#define SLOT(s, arr) (st + ((s) * 3 + (arr)) * THREADS)

        // prologue: fill STAGES groups (possibly empty-guarded)
#pragma unroll
        for (int k = 0; k < STAGES; ++k) {
            int i = t + k * THREADS;
            if (k < KTOT && i < cnt) {
                cp16(SLOT(k, 0), pp + base + i);
                cp16(SLOT(k, 1), ll + base + i);
                cp16(SLOT(k, 2), ww + base + i);
            }
            CP_COMMIT();
        }

        int slot = 0;
        for (int k = 0; k < KTOT; ++k) {
            CP_WAIT2();                                  // oldest group done
            const int i = t + k * THREADS;
            if (i < cnt) {
                float4 pv = *SLOT(slot, 0);
                float4 lv = *SLOT(slot, 1);
                float4 wv = *SLOT(slot, 2);
#define DO_COMP(c)                                                        \
                {                                                         \
                    float offf = fmaf(lv.c, -(float)NB,                   \
                                      fmaf(pv.c, (float)NB, (float)NB));  \
                    atomicAdd(sh + (int)offf, wv.c);                      \
                }
                DO_COMP(x) DO_COMP(y) DO_COMP(z) DO_COMP(w)
#undef DO_COMP
            }
            // refill this slot with stage k+STAGES
            const int kn = k + STAGES;
            const int i2 = t + kn * THREADS;
            if (kn < KTOT && i2 < cnt) {
                cp16(SLOT(slot, 0), pp + base + i2);
                cp16(SLOT(slot, 1), ll + base + i2);
                cp16(SLOT(slot, 2), ww + base + i2);
            }
            CP_COMMIT();
            slot = (slot + 1 == STAGES) ? 0 : slot + 1;
        }
        CP_WAIT0();
#undef SLOT
    }
    __syncthreads();

    // ---- flush to global ----
    float* gh = g_hist + task * 2 * NB;
    for (int i = t; i < 2 * NB; i += THREADS)
        atomicAdd(gh + i, sh[i]);
    __threadfence();
    __syncthreads();

    // ---- elect last block per task ----
    __shared__ unsigned s_last;
    if (t == 0) s_last = atomicAdd(&g_count[task], 1u);
    __syncthreads();
    if (s_last != CHUNKS - 1) return;
    __threadfence();   // acquire: see all other blocks' hist atomics

    // ---- finalize (this block only): suffix scan + area + auc ----
    float* fsum = sh;
    float  th[BINS_PT], loc[BINS_PT];
    float  s = 0.0f;
#pragma unroll
    for (int j = BINS_PT - 1; j >= 0; --j) {
        th[j] = gh[t * BINS_PT + j];
        s += th[j];
        loc[j] = s;
    }
    __syncthreads();
    fsum[t] = s;
    __syncthreads();

    for (int off = 1; off < THREADS; off <<= 1) {
        float v = (t + off < THREADS) ? fsum[t + off] : 0.0f;
        __syncthreads();
        fsum[t] += v;
        __syncthreads();
    }
    const float above    = (t + 1 < THREADS) ? fsum[t + 1] : 0.0f;
    const float tp_total = fsum[0];
    __syncthreads();

    double a = 0.0, f = 0.0;
#pragma unroll
    for (int j = 0; j < BINS_PT; ++j) {
        float fv  = gh[NB + t * BINS_PT + j];
        float lut = above + loc[j] - 0.5f * th[j];
        a += (double)fv * (double)lut;
        f += (double)fv;
    }

#pragma unroll
    for (int off = 16; off; off >>= 1) {
        a += __shfl_down_sync(0xffffffffu, a, off);
        f += __shfl_down_sync(0xffffffffu, f, off);
    }
    double* sred = (double*)sh;
    const int warp = t >> 5, lane = t & 31;
    __syncthreads();
    if (lane == 0) { sred[warp] = a; sred[16 + warp] = f; }
    __syncthreads();

    if (t == 0) {
        double ta = 0.0, tf = 0.0;
#pragma unroll
        for (int k = 0; k < THREADS / 32; ++k) { ta += sred[k]; tf += sred[16 + k]; }
        double denom = tf * (double)tp_total;
        out[task] = (denom == 0.0) ? 0.5f : (float)(ta / denom);
        g_count[task] = 0u;
    }

    for (int i = t; i < 2 * NB; i += THREADS) gh[i] = 0.0f;
}

extern "C" void kernel_launch(void* const* d_in, const int* in_sizes, int n_in,
                              void* d_out, int out_size) {
    int off = (n_in >= 4 && in_sizes[0] == 1) ? 1 : 0;
    const float4* p = (const float4*)d_in[off + 0];
    const float4* l = (const float4*)d_in[off + 1];
    const float4* w = (const float4*)d_in[off + 2];

    static int attr_set = 0;   // idempotent attribute set (not a work guard)
    if (!attr_set) {
        cudaFuncSetAttribute(auc_kernel,
                             cudaFuncAttributeMaxDynamicSharedMemorySize,
                             SMEM_BYTES);
        attr_set = 1;
    }

    dim3 g(CHUNKS, T_TASKS);
    auc_kernel<<<g, THREADS, SMEM_BYTES>>>(p, l, w, (float*)d_out);
}